// round 7
// baseline (speedup 1.0000x reference)
#include <cuda_runtime.h>
#include <cstdint>

// ---------------------------------------------------------------------------
// HOSVD aggregator, rank-1 factored core (register-lean j-sum):
//   ris[n,d,r] = sum_i x[n,d,i] * U_stack[d,i,r]            (proj)
//   q[n,k=g2*8+g3] = ris3[g2]*ris2[g3]
//   G3[m1,k,j=g0*8+g4] = G[g0,m1,g2,g3,g4]
//   jsum(m,k) = sum_g0 ris0[g0] * sum_g4 ris1[g4]*G3[m,k,g0,g4]
//   V[n,m1]  = sum_k q_k * jsum(m1,k)                       (core, f32x2)
//   out[n,o] = sum_m1 V[n,m1] * U_output[m1,o]              (vout)
// ---------------------------------------------------------------------------

#define MAXN 65536

__device__ float g_R [(size_t)MAXN * 32];   // per-sample ris (4x8)
__device__ float g_V [(size_t)MAXN * 8];    // per-sample v[m1]
__device__ float g_G3[32768];
__device__ float g_Ut[8192];

#define FMA2(d, a, b, c) \
    asm("fma.rn.f32x2 %0, %1, %2, %3;" : "=l"(d) : "l"(a), "l"(b), "l"(c))
#define MUL2(d, a, b) \
    asm("mul.rn.f32x2 %0, %1, %2;" : "=l"(d) : "l"(a), "l"(b))
#define ADD2(d, a, b) \
    asm("add.rn.f32x2 %0, %1, %2;" : "=l"(d) : "l"(a), "l"(b))
#define PACK2(d, lo, hi) \
    asm("mov.b64 %0, {%1, %2};" : "=l"(d) : "f"(lo), "f"(hi))
#define UNPACK2(lo, hi, s) \
    asm("mov.b64 {%0, %1}, %2;" : "=f"(lo), "=f"(hi) : "l"(s))

// ---------------------------------------------------------------------------
// prep: permute G -> G3, transpose U_stack -> U_t[d][r][i]
// ---------------------------------------------------------------------------
__global__ void prep_kernel(const float* __restrict__ G,
                            const float* __restrict__ U) {
    int t = blockIdx.x * blockDim.x + threadIdx.x;
    if (t < 32768) {
        int m1 = t >> 12;
        int k  = (t >> 6) & 63;
        int j  = t & 63;
        int g0 = j >> 3, g4 = j & 7;
        int g2 = k >> 3, g3i = k & 7;
        g_G3[t] = G[g0 * 4096 + m1 * 512 + g2 * 64 + g3i * 8 + g4];
    }
    if (t < 8192) {
        int d = t >> 11;
        int r = (t >> 8) & 7;
        int i = t & 255;
        g_Ut[t] = U[d * 2048 + i * 8 + r];
    }
}

// ---------------------------------------------------------------------------
// proj: warp per sample -> ris (32 floats per sample)
// ---------------------------------------------------------------------------
__global__ void __launch_bounds__(256) proj_kernel(
        const float* __restrict__ X, int N) {
    extern __shared__ float sm[];
    float* Ut  = sm;              // 8192 floats
    float* red = sm + 8192;       // 8 * 32*33 floats

    int tid = threadIdx.x;
    int w   = tid >> 5;
    int l   = tid & 31;

    for (int i = tid; i < 8192; i += 256) Ut[i] = g_Ut[i];
    __syncthreads();

    const float4* Ut4   = (const float4*)Ut;
    float*        myred = red + w * (32 * 33);
    int warpsTotal = gridDim.x * 8;

    for (int n = blockIdx.x * 8 + w; n < N; n += warpsTotal) {
        const float4* X4 = (const float4*)X + (size_t)n * 256;
        float4 a[8];
#pragma unroll
        for (int q = 0; q < 8; q++) a[q] = X4[q * 32 + l];

        float p[32];
#pragma unroll
        for (int t = 0; t < 32; t++) p[t] = 0.f;

#pragma unroll
        for (int q = 0; q < 8; q++) {
            const int d    = q >> 1;
            const int base = ((q & 1) << 5) + l;
#pragma unroll
            for (int r = 0; r < 8; r++) {
                float4 u = Ut4[(d * 8 + r) * 64 + base];
                p[d * 8 + r] += a[q].x * u.x + a[q].y * u.y
                              + a[q].z * u.z + a[q].w * u.w;
            }
        }

#pragma unroll
        for (int t = 0; t < 32; t++) myred[t * 33 + l] = p[t];
        __syncwarp();
        float s = 0.f;
#pragma unroll
        for (int i = 0; i < 32; i++) s += myred[l * 33 + i];
        // lane l = d*8+r holds ris[d][r]

        g_R[(size_t)n * 32 + l] = s;
        __syncwarp();
    }
}

// ---------------------------------------------------------------------------
// core: lane per sample, task = (32-sample block, m-pair).
// j-sum factored through ris0/ris1 -> no P materialization, ~85 regs.
// smem: G3 (32768 f) + r3 staging (16 warps * 256 f)
// ---------------------------------------------------------------------------
__global__ void __launch_bounds__(512) core_kernel(int N) {
    extern __shared__ float sm[];
    float* G3s = sm;                 // 32768 floats
    float* r3s = sm + 32768;         // 16 * 256 floats

    int tid = threadIdx.x;
    int w   = tid >> 5;
    int l   = tid & 31;

    for (int i = tid; i < 32768; i += 512) G3s[i] = g_G3[i];
    __syncthreads();

    const ulonglong2* G3v = (const ulonglong2*)G3s;   // 4 floats / elem
    float* myr3 = r3s + w * 256;

    int nblocks = (N + 31) >> 5;
    int ntasks  = nblocks * 4;                        // 4 m-pairs per block
    int tstride = gridDim.x * 16;

    for (int task = blockIdx.x + gridDim.x * w; task < ntasks; task += tstride) {
        int sb = task >> 2;          // sample block
        int q  = task & 3;           // m-quarter
        int m0 = q * 2;

        int n  = sb * 32 + l;
        int nc = (n < N) ? n : (N - 1);

        // load this lane's ris (32 floats)
        float4 risv[8];
        const float4* Rp = (const float4*)(g_R + (size_t)nc * 32);
#pragma unroll
        for (int i = 0; i < 8; i++) risv[i] = __ldg(Rp + i);

        // ris0 -> dup pairs (16 regs), ris1 -> adjacent pairs (8 regs),
        // ris2 -> scalars (8 regs), ris3 -> smem staging
        unsigned long long r0d[8], rp1[4];
        float ris2s[8];
        {
            const float ris0[8] = { risv[0].x, risv[0].y, risv[0].z, risv[0].w,
                                    risv[1].x, risv[1].y, risv[1].z, risv[1].w };
            const float ris1[8] = { risv[2].x, risv[2].y, risv[2].z, risv[2].w,
                                    risv[3].x, risv[3].y, risv[3].z, risv[3].w };
#pragma unroll
            for (int g0 = 0; g0 < 8; g0++) PACK2(r0d[g0], ris0[g0], ris0[g0]);
#pragma unroll
            for (int t = 0; t < 4; t++)
                PACK2(rp1[t], ris1[2 * t], ris1[2 * t + 1]);
            ris2s[0] = risv[4].x; ris2s[1] = risv[4].y;
            ris2s[2] = risv[4].z; ris2s[3] = risv[4].w;
            ris2s[4] = risv[5].x; ris2s[5] = risv[5].y;
            ris2s[6] = risv[5].z; ris2s[7] = risv[5].w;
            const float ris3[8] = { risv[6].x, risv[6].y, risv[6].z, risv[6].w,
                                    risv[7].x, risv[7].y, risv[7].z, risv[7].w };
#pragma unroll
            for (int g2 = 0; g2 < 8; g2++) myr3[g2 * 32 + l] = ris3[g2];
        }
        __syncwarp();

        unsigned long long v2[2];
        v2[0] = 0ull; v2[1] = 0ull;

        for (int g2 = 0; g2 < 8; g2++) {
            float r3c = myr3[g2 * 32 + l];
#pragma unroll
            for (int g3 = 0; g3 < 8; g3++) {
                int k = g2 * 8 + g3;
                float qk = r3c * ris2s[g3];
                unsigned long long qk2;
                PACK2(qk2, qk, qk);
#pragma unroll
                for (int m = 0; m < 2; m++) {
                    const ulonglong2* gp = G3v + (m0 + m) * 1024 + k * 16;
                    unsigned long long accE = 0ull, accO = 0ull;
#pragma unroll
                    for (int g0 = 0; g0 < 8; g0 += 2) {
                        ulonglong2 ga = gp[g0 * 2];
                        ulonglong2 gb = gp[g0 * 2 + 1];
                        ulonglong2 gc = gp[g0 * 2 + 2];
                        ulonglong2 gd = gp[g0 * 2 + 3];
                        unsigned long long s0 = 0ull, s1 = 0ull;
                        FMA2(s0, rp1[0], ga.x, s0);
                        FMA2(s1, rp1[0], gc.x, s1);
                        FMA2(s0, rp1[1], ga.y, s0);
                        FMA2(s1, rp1[1], gc.y, s1);
                        FMA2(s0, rp1[2], gb.x, s0);
                        FMA2(s1, rp1[2], gd.x, s1);
                        FMA2(s0, rp1[3], gb.y, s0);
                        FMA2(s1, rp1[3], gd.y, s1);
                        FMA2(accE, r0d[g0],     s0, accE);
                        FMA2(accO, r0d[g0 + 1], s1, accO);
                    }
                    unsigned long long acc;
                    ADD2(acc, accE, accO);
                    FMA2(v2[m], acc, qk2, v2[m]);
                }
            }
        }

        float lo0, hi0, lo1, hi1;
        UNPACK2(lo0, hi0, v2[0]);
        UNPACK2(lo1, hi1, v2[1]);
        float2 vout = make_float2(lo0 + hi0, lo1 + hi1);
        *(float2*)(g_V + (size_t)nc * 8 + m0) = vout;

        __syncwarp();   // myr3 reuse next task
    }
}

// ---------------------------------------------------------------------------
// vout: persistent; Uo in smem once per block; warp per sample, V prefetch.
// ---------------------------------------------------------------------------
__global__ void __launch_bounds__(256) vout_kernel(
        const float* __restrict__ Uo,
        float* __restrict__ out, int N) {
    __shared__ float Uos[1024];
    int tid = threadIdx.x;
    for (int i = tid; i < 1024; i += 256) Uos[i] = Uo[i];
    __syncthreads();

    const float4* Uo4 = (const float4*)Uos;
    int w  = tid >> 5;
    int o4 = tid & 31;
    int stride = gridDim.x * 8;

    int n = blockIdx.x * 8 + w;
    if (n >= N) return;

    const float4* vp = (const float4*)g_V;
    float4 va = __ldg(vp + (size_t)n * 2);
    float4 vb = __ldg(vp + (size_t)n * 2 + 1);

    while (true) {
        int nn = n + stride;
        float4 wa, wb;
        if (nn < N) {
            wa = __ldg(vp + (size_t)nn * 2);
            wb = __ldg(vp + (size_t)nn * 2 + 1);
        }

        float vm[8] = { va.x, va.y, va.z, va.w, vb.x, vb.y, vb.z, vb.w };
        float4 acc = make_float4(0.f, 0.f, 0.f, 0.f);
#pragma unroll
        for (int m = 0; m < 8; m++) {
            float4 u = Uo4[m * 32 + o4];
            acc.x += vm[m] * u.x; acc.y += vm[m] * u.y;
            acc.z += vm[m] * u.z; acc.w += vm[m] * u.w;
        }
        ((float4*)out)[(size_t)n * 32 + o4] = acc;

        if (nn >= N) break;
        n = nn;
        va = wa; vb = wb;
    }
}

// ---------------------------------------------------------------------------
extern "C" void kernel_launch(void* const* d_in, const int* in_sizes, int n_in,
                              void* d_out, int out_size) {
    const float* X  = (const float*)d_in[0];   // [N,4,256]
    const float* G  = (const float*)d_in[1];   // [8,8,8,8,8]
    const float* U  = (const float*)d_in[2];   // [4,256,8]
    const float* Uo = (const float*)d_in[3];   // [8,128]
    float* out = (float*)d_out;

    int N = in_sizes[0] / 1024;
    if (N > MAXN) N = MAXN;

    prep_kernel<<<128, 256>>>(G, U);

    const int kA_smem = (8192 + 8 * 32 * 33) * (int)sizeof(float);
    cudaFuncSetAttribute(proj_kernel,
                         cudaFuncAttributeMaxDynamicSharedMemorySize, kA_smem);
    proj_kernel<<<444, 256, kA_smem>>>(X, N);

    const int kB_smem = (32768 + 16 * 256) * (int)sizeof(float);   // 144 KB
    cudaFuncSetAttribute(core_kernel,
                         cudaFuncAttributeMaxDynamicSharedMemorySize, kB_smem);
    core_kernel<<<148, 512, kB_smem>>>(N);

    vout_kernel<<<148, 256>>>(Uo, out, N);
}